// round 2
// baseline (speedup 1.0000x reference)
#include <cuda_runtime.h>

#define N_ALPHA 0.05f
#define N_BETA  0.95f
#define BC_TOT  128
#define NN      1024
#define HID     20
#define KC      16

// scratch: h0..h3 and 1/rowsum
__device__ float g_h[4][BC_TOT * NN * HID];
__device__ float g_invrs[BC_TOT * NN];

static __device__ __forceinline__ unsigned long long fma2(unsigned long long a,
                                                          unsigned long long b,
                                                          unsigned long long c) {
    unsigned long long d;
    asm("fma.rn.f32x2 %0, %1, %2, %3;" : "=l"(d) : "l"(a), "l"(b), "l"(c));
    return d;
}
static __device__ __forceinline__ unsigned long long pack2(float x, float y) {
    unsigned long long d;
    asm("mov.b64 %0, {%1, %2};" : "=l"(d) : "f"(x), "f"(y));
    return d;
}
static __device__ __forceinline__ float2 unpack2(unsigned long long v) {
    float2 f;
    asm("mov.b64 {%0, %1}, %2;" : "=f"(f.x), "=f"(f.y) : "l"(v));
    return f;
}

// ---------------------------------------------------------------------------
// h0[bc][n][j] = sum_i x[b][i][n][c] * Ws[i][j] + bs[j]
// ---------------------------------------------------------------------------
__global__ void h0_kernel(const float* __restrict__ x,
                          const float* __restrict__ Ws,
                          const float* __restrict__ bs) {
    __shared__ float wsm[32 * HID];
    __shared__ float bsm[HID];
    int tid = threadIdx.x;
    for (int i = tid; i < 32 * HID; i += 256) wsm[i] = Ws[i];
    if (tid < HID) bsm[tid] = bs[tid];
    __syncthreads();

    int r = blockIdx.x * 256 + tid;          // 0..131071
    int c = r & 15;
    int n = (r >> 4) & 1023;
    int b = r >> 14;

    unsigned long long acc[10];
    const unsigned long long* bp = (const unsigned long long*)bsm;
#pragma unroll
    for (int j = 0; j < 10; j++) acc[j] = bp[j];

    const float* xp = x + (size_t)b * 32 * 16384 + n * 16 + c;
#pragma unroll
    for (int i = 0; i < 32; i++) {
        float xv = xp[(size_t)i * 16384];
        unsigned long long xv2 = pack2(xv, xv);
        const unsigned long long* wr = (const unsigned long long*)&wsm[i * HID];
#pragma unroll
        for (int j = 0; j < 10; j++) acc[j] = fma2(xv2, wr[j], acc[j]);
    }
    int bc = b * 16 + c;
    float* o = &g_h[0][((size_t)bc * NN + n) * HID];
#pragma unroll
    for (int j = 0; j < 10; j++) {
        float2 f = unpack2(acc[j]);
        o[2 * j] = f.x; o[2 * j + 1] = f.y;
    }
}

// ---------------------------------------------------------------------------
// One propagation pass:
//   h_dst[v] = alpha*h0[v] + beta * (adj[v,:]@h_src + h_src[v]) / rowsum[v]
// FIRST pass also computes rowsum[v] = sum_w adj[v,w] + 1 on the fly.
// grid (2, 128), block 256; each thread owns 2 full rows (complete K in-thread)
// ---------------------------------------------------------------------------
template <bool FIRST>
__global__ void prop_kernel(const float* __restrict__ adj, int src, int dst) {
    __shared__ float adj_s[512 * 17];      // pad 17 -> conflict-free column reads
    __shared__ float hs[KC * HID];         // current h chunk [16][20]

    int bc = blockIdx.y;
    int rowbase = blockIdx.x * 512;
    int tid = threadIdx.x;

    const float* adjbc = adj + (size_t)bc * NN * NN + (size_t)rowbase * NN;
    const float* hp = &g_h[src][(size_t)bc * NN * HID];

    unsigned long long acc0[10], acc1[10];
#pragma unroll
    for (int j = 0; j < 10; j++) { acc0[j] = 0ull; acc1[j] = 0ull; }
    float rs0 = 0.f, rs1 = 0.f;

    for (int wc = 0; wc < NN / KC; wc++) {
        __syncthreads();
        // stage adj chunk: 512 rows x 16 cols, coalesced 64B strips per row
#pragma unroll
        for (int p = 0; p < 8; p++) {
            int idx = tid + p * 256;             // 0..2047 float4's
            int vl = idx >> 2;
            int w4 = (idx & 3) << 2;
            float4 f = *(const float4*)(adjbc + (size_t)vl * NN + wc * KC + w4);
            float* d = &adj_s[vl * 17 + w4];
            d[0] = f.x; d[1] = f.y; d[2] = f.z; d[3] = f.w;
        }
        // stage h chunk: 16*20 floats
        if (tid < (KC * HID) / 4) {
            *(float4*)&hs[tid * 4] = *(const float4*)(hp + wc * (KC * HID) + tid * 4);
        }
        __syncthreads();

#pragma unroll
        for (int w = 0; w < KC; w++) {
            float a0 = adj_s[tid * 17 + w];
            float a1 = adj_s[(tid + 256) * 17 + w];
            if (FIRST) { rs0 += a0; rs1 += a1; }
            unsigned long long a02 = pack2(a0, a0);
            unsigned long long a12 = pack2(a1, a1);
            // h row: 20 floats = 5x LDS.128 broadcast, already f32x2-paired
            const ulonglong2* hw2 = (const ulonglong2*)&hs[w * HID];
            ulonglong2 q0 = hw2[0], q1 = hw2[1], q2 = hw2[2], q3 = hw2[3], q4 = hw2[4];
            unsigned long long hv[10] = {q0.x, q0.y, q1.x, q1.y, q2.x,
                                         q2.y, q3.x, q3.y, q4.x, q4.y};
#pragma unroll
            for (int j = 0; j < 10; j++) {
                acc0[j] = fma2(a02, hv[j], acc0[j]);
                acc1[j] = fma2(a12, hv[j], acc1[j]);
            }
        }
    }

    int v0 = rowbase + tid;
    int v1 = v0 + 256;
    float ir0, ir1;
    if (FIRST) {
        ir0 = 1.f / (rs0 + 1.f);
        ir1 = 1.f / (rs1 + 1.f);
        g_invrs[bc * NN + v0] = ir0;
        g_invrs[bc * NN + v1] = ir1;
    } else {
        ir0 = g_invrs[bc * NN + v0];
        ir1 = g_invrs[bc * NN + v1];
    }

    const float* h0p = &g_h[0][(size_t)bc * NN * HID];
    float* ho = &g_h[dst][(size_t)bc * NN * HID];
    {
        const float* hpr = hp + v0 * HID;
        const float* h0r = h0p + v0 * HID;
        float* outr = ho + v0 * HID;
#pragma unroll
        for (int j = 0; j < 10; j++) {
            float2 a = unpack2(acc0[j]);
            outr[2 * j]     = N_ALPHA * h0r[2 * j]     + N_BETA * (a.x + hpr[2 * j]) * ir0;
            outr[2 * j + 1] = N_ALPHA * h0r[2 * j + 1] + N_BETA * (a.y + hpr[2 * j + 1]) * ir0;
        }
    }
    {
        const float* hpr = hp + v1 * HID;
        const float* h0r = h0p + v1 * HID;
        float* outr = ho + v1 * HID;
#pragma unroll
        for (int j = 0; j < 10; j++) {
            float2 a = unpack2(acc1[j]);
            outr[2 * j]     = N_ALPHA * h0r[2 * j]     + N_BETA * (a.x + hpr[2 * j]) * ir1;
            outr[2 * j + 1] = N_ALPHA * h0r[2 * j + 1] + N_BETA * (a.y + hpr[2 * j + 1]) * ir1;
        }
    }
}

// ---------------------------------------------------------------------------
// out[bc][n][o] = sum_{p,j} h_p[bc][n][j] * We[(p*20+j)][o] + be[o]
// ---------------------------------------------------------------------------
__global__ void end_kernel(const float* __restrict__ We,
                           const float* __restrict__ be,
                           float* __restrict__ out) {
    __shared__ float wsm[80 * 32];
    __shared__ float bsm[32];
    int tid = threadIdx.x;
    for (int i = tid; i < 80 * 32; i += 256) wsm[i] = We[i];
    if (tid < 32) bsm[tid] = be[tid];
    __syncthreads();

    int r = blockIdx.x * 256 + tid;       // r = bc*1024 + n
    unsigned long long acc[16];
    const unsigned long long* bp = (const unsigned long long*)bsm;
#pragma unroll
    for (int o = 0; o < 16; o++) acc[o] = bp[o];

    size_t rowoff = (size_t)r * HID;
#pragma unroll
    for (int p = 0; p < 4; p++) {
        const float* hr = &g_h[p][rowoff];
#pragma unroll
        for (int j4 = 0; j4 < 5; j4++) {
            float4 f = *(const float4*)(hr + j4 * 4);
            float vs[4] = {f.x, f.y, f.z, f.w};
#pragma unroll
            for (int u = 0; u < 4; u++) {
                unsigned long long v2 = pack2(vs[u], vs[u]);
                const unsigned long long* wr =
                    (const unsigned long long*)&wsm[(p * HID + j4 * 4 + u) * 32];
#pragma unroll
                for (int o = 0; o < 16; o++) acc[o] = fma2(v2, wr[o], acc[o]);
            }
        }
    }
    float* op = out + (size_t)r * 32;
#pragma unroll
    for (int o = 0; o < 16; o++) {
        float2 f = unpack2(acc[o]);
        op[2 * o] = f.x; op[2 * o + 1] = f.y;
    }
}

// ---------------------------------------------------------------------------
extern "C" void kernel_launch(void* const* d_in, const int* in_sizes, int n_in,
                              void* d_out, int out_size) {
    const float* x   = (const float*)d_in[0];
    const float* adj = (const float*)d_in[1];
    const float* Ws  = (const float*)d_in[2];
    const float* bs  = (const float*)d_in[3];
    const float* We  = (const float*)d_in[4];
    const float* be  = (const float*)d_in[5];
    float* out = (float*)d_out;

    h0_kernel<<<512, 256>>>(x, Ws, bs);
    prop_kernel<true><<<dim3(2, 128), 256>>>(adj, 0, 1);
    prop_kernel<false><<<dim3(2, 128), 256>>>(adj, 1, 2);
    prop_kernel<false><<<dim3(2, 128), 256>>>(adj, 2, 3);
    end_kernel<<<512, 256>>>(We, be, out);
}